// round 13
// baseline (speedup 1.0000x reference)
#include <cuda_runtime.h>
#include <cstdint>

// Motion loss on GB300: warp-specialized packed-f32x2 FK (R10/R11 compute),
// at 8 blocks/SM granularity: 32 rows / 64 threads / ~27.8 KB smem. Eight
// independent load/compute contexts per SM keep DRAM streaming while other
// blocks compute (R11 confirmed the phase-overlap mechanism at 4 blocks/SM:
// 36.9 -> 33.2 us, DRAM 36 -> 39%).

namespace {

constexpr int ROW   = 99;                  // floats per row (per array)
constexpr int RPB   = 32;                  // rows per block
constexpr int TPB   = 64;                  // 2 threads per row (A-warp + B-warp)
constexpr int NBT   = 64 * 2048;           // 131072 rows
constexpr int NBLK  = NBT / RPB;           // 4096 blocks
constexpr int TILE_F4 = RPB * ROW / 4;     // 792 float4 per array per tile

constexpr int PAIRS     = RPB * ROW;       // 3168 u64 pairs
constexpr int BONES_OFF = PAIRS;           // u64 units
constexpr int G9_OFF    = BONES_OFF + 72;  // u64 units
constexpr int SMEM_BYTES = (G9_OFF + RPB * 7 + 8) * 8;   // ~27.8 KB

// joint terms owned by exactly one thread -> full weight
constexpr float S1 = 1.0f / (float(NBT) * 96.0f);
constexpr float S2 = 2.5f / (float(NBT) * 72.0f);
// root terms computed by both threads of a row -> half weight
constexpr float S1h  = 0.5f * S1;
constexpr float S23h = 0.5f * (S2 + 1.0f / (float(NBT) * 3.0f));

} // namespace

__device__ float    g_partials[NBLK];
__device__ unsigned g_count = 0;

using u32 = unsigned int;
using u64 = unsigned long long;

// ---- packed f32x2 primitives ----
__device__ __forceinline__ u64 pk2(float lo, float hi) {
    u64 r;
    asm("mov.b64 %0, {%1, %2};" : "=l"(r)
        : "r"(__float_as_uint(lo)), "r"(__float_as_uint(hi)));
    return r;
}
__device__ __forceinline__ void upk2(u64 v, float& lo, float& hi) {
    u32 a, b;
    asm("mov.b64 {%0, %1}, %2;" : "=r"(a), "=r"(b) : "l"(v));
    lo = __uint_as_float(a); hi = __uint_as_float(b);
}
__device__ __forceinline__ u64 fm2(u64 a, u64 b, u64 c) {
    u64 r; asm("fma.rn.f32x2 %0, %1, %2, %3;" : "=l"(r) : "l"(a), "l"(b), "l"(c));
    return r;
}
__device__ __forceinline__ u64 ml2(u64 a, u64 b) {
    u64 r; asm("mul.rn.f32x2 %0, %1, %2;" : "=l"(r) : "l"(a), "l"(b));
    return r;
}
__device__ __forceinline__ u64 ad2(u64 a, u64 b) {
    u64 r; asm("add.rn.f32x2 %0, %1, %2;" : "=l"(r) : "l"(a), "l"(b));
    return r;
}

constexpr u64 NEG1 = 0xBF800000BF800000ULL;
constexpr u64 TWO  = 0x4000000040000000ULL;

struct PXf { u64 qw, qx, qy, qz, tx, ty, tz; };

// (hi-lo)^2 accumulate
__device__ __forceinline__ void d2(u64 v, float& s) {
    float a, b; upk2(v, a, b);
    float d = a - b;
    s = fmaf(d, d, s);
}

__device__ __forceinline__ void pcompose(const PXf& p,
                                         u64 lw, u64 lx, u64 ly, u64 lz,
                                         u64 bx, u64 by, u64 bz, PXf& o) {
    u64 nx = ml2(p.qx, NEG1), ny = ml2(p.qy, NEG1), nz = ml2(p.qz, NEG1);
    u64 cx = fm2(p.qy, bz, ml2(nz, by));
    u64 cy = fm2(p.qz, bx, ml2(nx, bz));
    u64 cz = fm2(p.qx, by, ml2(ny, bx));
    u64 sx = fm2(p.qw, cx, fm2(p.qy, cz, ml2(nz, cy)));
    u64 sy = fm2(p.qw, cy, fm2(p.qz, cx, ml2(nx, cz)));
    u64 sz = fm2(p.qw, cz, fm2(p.qx, cy, ml2(ny, cx)));
    o.tx = fm2(TWO, sx, ad2(bx, p.tx));
    o.ty = fm2(TWO, sy, ad2(by, p.ty));
    o.tz = fm2(TWO, sz, ad2(bz, p.tz));
    u64 rw = fm2(p.qw, lw, fm2(nx, lx, fm2(ny, ly, ml2(nz, lz))));
    u64 rx = fm2(p.qw, lx, fm2(lw, p.qx, fm2(p.qy, lz, ml2(nz, ly))));
    u64 ry = fm2(p.qw, ly, fm2(lw, p.qy, fm2(p.qz, lx, ml2(nx, lz))));
    u64 rz = fm2(p.qw, lz, fm2(lw, p.qz, fm2(p.qx, ly, ml2(ny, lx))));
    o.qw = rw; o.qx = rx; o.qy = ry; o.qz = rz;
}

// one non-root joint (both skeletons); j is compile-time constant at call site
__device__ __forceinline__ void jstep(const u64* __restrict__ r,
                                      const u64* __restrict__ bn,
                                      int j, const PXf& P, PXf& O, float& acc) {
    u64 w = r[4*j+0], x = r[4*j+1], y = r[4*j+2], z = r[4*j+3];

    u64 n2 = ml2(w, w); n2 = fm2(x, x, n2); n2 = fm2(y, y, n2); n2 = fm2(z, z, n2);
    float na, nb; upk2(n2, na, nb);
    u64 inv = pk2(rsqrtf(na), rsqrtf(nb));
    w = ml2(w, inv); x = ml2(x, inv); y = ml2(y, inv); z = ml2(z, inv);

    float s = 0.f;
    d2(w, s); d2(x, s); d2(y, s); d2(z, s);
    acc = fmaf(S1, s, acc);

    pcompose(P, w, x, y, z, bn[3*j+0], bn[3*j+1], bn[3*j+2], O);

    float t = 0.f;
    d2(O.tx, t); d2(O.ty, t); d2(O.tz, t);
    acc = fmaf(S2, t, acc);
}

__global__ __launch_bounds__(TPB, 8)
void motion_loss_kernel(const float* __restrict__ Ym,
                        const float* __restrict__ Xm,
                        const float* __restrict__ Yt,
                        const float* __restrict__ Xt,
                        float* __restrict__ out)
{
    extern __shared__ float sm[];
    const int tid = threadIdx.x;
    const int bid = blockIdx.x;

    // ---- stage interleaved (x,y) pairs: coalesced LDG.128 -> STS.128 ----
    {
        const float4* gx = (const float4*)(Xm + (size_t)bid * RPB * ROW);
        const float4* gy = (const float4*)(Ym + (size_t)bid * RPB * ROW);
        float4* d = (float4*)sm;
        #pragma unroll
        for (int k = 0; k < 13; ++k) {
            int i = tid + k * TPB;
            if (i < TILE_F4) {
                float4 a = __ldg(gx + i);
                float4 c = __ldg(gy + i);
                d[2*i + 0] = make_float4(a.x, c.x, a.y, c.y);
                d[2*i + 1] = make_float4(a.z, c.z, a.w, c.w);
            }
        }
    }

    // ---- stage packed bone table (72 u64 pairs) ----
    const int b = bid >> 6;                    // 64 blocks per batch item
    {
        float2* bt = (float2*)sm + BONES_OFF;
        #pragma unroll
        for (int i = tid; i < 72; i += TPB)
            bt[i] = make_float2(Xt[b * 72 + i], Yt[b * 72 + i]);
    }
    __syncthreads();

    const int lane = tid & 31;
    const int wid  = tid >> 5;                 // 0..1
    const int isB  = wid & 1;                  // warp 0 = half A, warp 1 = half B
    const int row  = lane;                     // row within tile (0..31)

    const u64* r  = (const u64*)sm + (size_t)row * ROW;
    const u64* bn = (const u64*)sm + BONES_OFF;
    u64* g9s      = (u64*)sm + G9_OFF + (size_t)row * 7;

    const unsigned FULL = 0xffffffffu;
    float acc = 0.f;

    // ---- root (both warps of a pair; half weights) ----
    PXf P0;
    {
        u64 w = r[0], x = r[1], y = r[2], z = r[3];
        u64 n2 = ml2(w, w); n2 = fm2(x, x, n2); n2 = fm2(y, y, n2); n2 = fm2(z, z, n2);
        float na, nb; upk2(n2, na, nb);
        u64 inv = pk2(rsqrtf(na), rsqrtf(nb));
        w = ml2(w, inv); x = ml2(x, inv); y = ml2(y, inv); z = ml2(z, inv);

        float s = 0.f;
        d2(w, s); d2(x, s); d2(y, s); d2(z, s);
        acc = fmaf(S1h, s, acc);

        P0.qw = w; P0.qx = x; P0.qy = y; P0.qz = z;
        P0.tx = r[96]; P0.ty = r[97]; P0.tz = r[98];
        float t = 0.f;
        d2(P0.tx, t); d2(P0.ty, t); d2(P0.tz, t);
        acc = fmaf(S23h, t, acc);
    }

    // ---- phase 1 ----
    PXf G9;                                    // A: chain 0->3->6->9 result
    if (!isB) {
        jstep(r, bn, 3, P0, G9, acc);
        jstep(r, bn, 6, G9, G9, acc);
        jstep(r, bn, 9, G9, G9, acc);
        g9s[0] = G9.qw; g9s[1] = G9.qx; g9s[2] = G9.qy; g9s[3] = G9.qz;
        g9s[4] = G9.tx; g9s[5] = G9.ty; g9s[6] = G9.tz;
    } else {
        PXf C;                                 // B: chain 0->2->5->8->11
        jstep(r, bn,  2, P0, C, acc);
        jstep(r, bn,  5, C,  C, acc);
        jstep(r, bn,  8, C,  C, acc);
        jstep(r, bn, 11, C,  C, acc);
    }
    __syncthreads();                           // publish G9 to the B warp

    // ---- phase 2: two independent chains per thread, interleaved ----
    if (!isB) {
        PXf C1, C2;
        jstep(r, bn,  1, P0, C1, acc);
        jstep(r, bn, 13, G9, C2, acc);
        jstep(r, bn,  4, C1, C1, acc);
        jstep(r, bn, 16, C2, C2, acc);
        jstep(r, bn,  7, C1, C1, acc);
        jstep(r, bn, 18, C2, C2, acc);
        jstep(r, bn, 10, C1, C1, acc);
        jstep(r, bn, 20, C2, C2, acc);
        jstep(r, bn, 22, C2, C2, acc);
    } else {
        PXf P9;
        P9.qw = g9s[0]; P9.qx = g9s[1]; P9.qy = g9s[2]; P9.qz = g9s[3];
        P9.tx = g9s[4]; P9.ty = g9s[5]; P9.tz = g9s[6];
        PXf C1, C2;
        jstep(r, bn, 12, P9, C1, acc);
        jstep(r, bn, 14, P9, C2, acc);
        jstep(r, bn, 15, C1, C1, acc);
        jstep(r, bn, 17, C2, C2, acc);
        jstep(r, bn, 19, C2, C2, acc);
        jstep(r, bn, 21, C2, C2, acc);
        jstep(r, bn, 23, C2, C2, acc);
    }

    // ---- block reduction (2 warps) ----
    #pragma unroll
    for (int o = 16; o > 0; o >>= 1) acc += __shfl_xor_sync(FULL, acc, o);

    __shared__ float wsum[2];
    __shared__ int   s_last;
    if (lane == 0) wsum[wid] = acc;
    __syncthreads();

    if (tid == 0) {
        g_partials[bid] = wsum[0] + wsum[1];
        __threadfence();
        unsigned ticket = atomicAdd(&g_count, 1u);
        s_last = (ticket == NBLK - 1) ? 1 : 0;
    }
    __syncthreads();

    // ---- last block: deterministic fixed-order final sum ----
    if (s_last) {
        double v = 0.0;
        #pragma unroll
        for (int k = 0; k < NBLK / TPB; ++k)     // 64 per thread
            v += (double)g_partials[tid + k * TPB];

        __shared__ double dsum[TPB];
        dsum[tid] = v;
        __syncthreads();
        #pragma unroll
        for (int o = TPB / 2; o > 0; o >>= 1) {
            if (tid < o) dsum[tid] += dsum[tid + o];
            __syncthreads();
        }
        if (tid == 0) {
            out[0] = (float)dsum[0];
            g_count = 0;                          // reset for next graph replay
        }
    }
}

extern "C" void kernel_launch(void* const* d_in, const int* in_sizes, int n_in,
                              void* d_out, int out_size)
{
    (void)in_sizes; (void)n_in; (void)out_size;
    const float* Ym = (const float*)d_in[0];
    const float* Xm = (const float*)d_in[1];
    const float* Yt = (const float*)d_in[2];
    const float* Xt = (const float*)d_in[3];

    cudaFuncSetAttribute(motion_loss_kernel,
                         cudaFuncAttributeMaxDynamicSharedMemorySize, SMEM_BYTES);
    motion_loss_kernel<<<NBLK, TPB, SMEM_BYTES>>>(Ym, Xm, Yt, Xt, (float*)d_out);
}

// round 15
// speedup vs baseline: 1.0683x; 1.0683x over previous
#include <cuda_runtime.h>
#include <cstdint>

// Motion loss on GB300: R11's warp-specialized packed-f32x2 FK (64 rows /
// 128 threads / 4 blocks/SM) with PAIR-SCOPED synchronization: warps {0,1}
// and {2,3} each stage their own 32-row subtile + bone copy and sync via
// named barriers (bar.sync id,64). Gives 8 independent load->compute
// contexts per SM. R13 fix: bone staging now strides ptid..72 by 64
// (previous `ptid < 72` guard left entries 64-71 unwritten -> rel_err 8e-3).

namespace {

constexpr int ROW   = 99;                  // floats per row (per array)
constexpr int RPB   = 64;                  // rows per block
constexpr int TPB   = 128;                 // 2 threads per row
constexpr int NBT   = 64 * 2048;           // 131072 rows
constexpr int NBLK  = NBT / RPB;           // 2048 blocks
constexpr int SUB_F4 = 32 * ROW / 4;       // 792 float4 per array per 32-row subtile

constexpr int SUB_PAIRS  = 32 * ROW;       // 3168 u64 pairs per subtile
constexpr int BONES_OFF  = 2 * SUB_PAIRS;  // u64 units (2 pair copies x 72)
constexpr int G9_OFF     = BONES_OFF + 2 * 72;
constexpr int SMEM_BYTES = (G9_OFF + RPB * 7 + 8) * 8;   // ~55.5 KB

// joint terms owned by exactly one thread -> full weight
constexpr float S1 = 1.0f / (float(NBT) * 96.0f);
constexpr float S2 = 2.5f / (float(NBT) * 72.0f);
// root terms computed by both threads of a row -> half weight
constexpr float S1h  = 0.5f * S1;
constexpr float S23h = 0.5f * (S2 + 1.0f / (float(NBT) * 3.0f));

} // namespace

__device__ float    g_partials[NBLK];
__device__ unsigned g_count = 0;

using u32 = unsigned int;
using u64 = unsigned long long;

// ---- packed f32x2 primitives ----
__device__ __forceinline__ u64 pk2(float lo, float hi) {
    u64 r;
    asm("mov.b64 %0, {%1, %2};" : "=l"(r)
        : "r"(__float_as_uint(lo)), "r"(__float_as_uint(hi)));
    return r;
}
__device__ __forceinline__ void upk2(u64 v, float& lo, float& hi) {
    u32 a, b;
    asm("mov.b64 {%0, %1}, %2;" : "=r"(a), "=r"(b) : "l"(v));
    lo = __uint_as_float(a); hi = __uint_as_float(b);
}
__device__ __forceinline__ u64 fm2(u64 a, u64 b, u64 c) {
    u64 r; asm("fma.rn.f32x2 %0, %1, %2, %3;" : "=l"(r) : "l"(a), "l"(b), "l"(c));
    return r;
}
__device__ __forceinline__ u64 ml2(u64 a, u64 b) {
    u64 r; asm("mul.rn.f32x2 %0, %1, %2;" : "=l"(r) : "l"(a), "l"(b));
    return r;
}
__device__ __forceinline__ u64 ad2(u64 a, u64 b) {
    u64 r; asm("add.rn.f32x2 %0, %1, %2;" : "=l"(r) : "l"(a), "l"(b));
    return r;
}

constexpr u64 NEG1 = 0xBF800000BF800000ULL;
constexpr u64 TWO  = 0x4000000040000000ULL;

struct PXf { u64 qw, qx, qy, qz, tx, ty, tz; };

// (hi-lo)^2 accumulate
__device__ __forceinline__ void d2(u64 v, float& s) {
    float a, b; upk2(v, a, b);
    float d = a - b;
    s = fmaf(d, d, s);
}

__device__ __forceinline__ void pcompose(const PXf& p,
                                         u64 lw, u64 lx, u64 ly, u64 lz,
                                         u64 bx, u64 by, u64 bz, PXf& o) {
    u64 nx = ml2(p.qx, NEG1), ny = ml2(p.qy, NEG1), nz = ml2(p.qz, NEG1);
    u64 cx = fm2(p.qy, bz, ml2(nz, by));
    u64 cy = fm2(p.qz, bx, ml2(nx, bz));
    u64 cz = fm2(p.qx, by, ml2(ny, bx));
    u64 sx = fm2(p.qw, cx, fm2(p.qy, cz, ml2(nz, cy)));
    u64 sy = fm2(p.qw, cy, fm2(p.qz, cx, ml2(nx, cz)));
    u64 sz = fm2(p.qw, cz, fm2(p.qx, cy, ml2(ny, cx)));
    o.tx = fm2(TWO, sx, ad2(bx, p.tx));
    o.ty = fm2(TWO, sy, ad2(by, p.ty));
    o.tz = fm2(TWO, sz, ad2(bz, p.tz));
    u64 rw = fm2(p.qw, lw, fm2(nx, lx, fm2(ny, ly, ml2(nz, lz))));
    u64 rx = fm2(p.qw, lx, fm2(lw, p.qx, fm2(p.qy, lz, ml2(nz, ly))));
    u64 ry = fm2(p.qw, ly, fm2(lw, p.qy, fm2(p.qz, lx, ml2(nx, lz))));
    u64 rz = fm2(p.qw, lz, fm2(lw, p.qz, fm2(p.qx, ly, ml2(ny, lx))));
    o.qw = rw; o.qx = rx; o.qy = ry; o.qz = rz;
}

// one non-root joint (both skeletons); j is compile-time constant at call site
__device__ __forceinline__ void jstep(const u64* __restrict__ r,
                                      const u64* __restrict__ bn,
                                      int j, const PXf& P, PXf& O, float& acc) {
    u64 w = r[4*j+0], x = r[4*j+1], y = r[4*j+2], z = r[4*j+3];

    u64 n2 = ml2(w, w); n2 = fm2(x, x, n2); n2 = fm2(y, y, n2); n2 = fm2(z, z, n2);
    float na, nb; upk2(n2, na, nb);
    u64 inv = pk2(rsqrtf(na), rsqrtf(nb));
    w = ml2(w, inv); x = ml2(x, inv); y = ml2(y, inv); z = ml2(z, inv);

    float s = 0.f;
    d2(w, s); d2(x, s); d2(y, s); d2(z, s);
    acc = fmaf(S1, s, acc);

    pcompose(P, w, x, y, z, bn[3*j+0], bn[3*j+1], bn[3*j+2], O);

    float t = 0.f;
    d2(O.tx, t); d2(O.ty, t); d2(O.tz, t);
    acc = fmaf(S2, t, acc);
}

// pair-scoped barrier: 64 threads of pair `pr` (barrier ids 1,2)
__device__ __forceinline__ void pair_sync(int pr) {
    asm volatile("bar.sync %0, 64;" :: "r"(pr + 1) : "memory");
}

__global__ __launch_bounds__(TPB, 4)
void motion_loss_kernel(const float* __restrict__ Ym,
                        const float* __restrict__ Xm,
                        const float* __restrict__ Yt,
                        const float* __restrict__ Xt,
                        float* __restrict__ out)
{
    extern __shared__ float sm[];
    const int tid  = threadIdx.x;
    const int bid  = blockIdx.x;
    const int pr   = tid >> 6;                 // pair 0: warps 0,1; pair 1: warps 2,3
    const int ptid = tid & 63;                 // thread index within the pair

    // ---- each pair stages ITS OWN 32-row subtile (interleaved (x,y)) ----
    {
        const size_t base = (size_t)bid * RPB * ROW + (size_t)pr * 32 * ROW;
        const float4* gx = (const float4*)(Xm + base);
        const float4* gy = (const float4*)(Ym + base);
        float4* d = (float4*)sm + (size_t)pr * 2 * SUB_F4;
        #pragma unroll
        for (int k = 0; k < 13; ++k) {
            int i = ptid + k * 64;
            if (i < SUB_F4) {
                float4 a = __ldg(gx + i);
                float4 c = __ldg(gy + i);
                d[2*i + 0] = make_float4(a.x, c.x, a.y, c.y);
                d[2*i + 1] = make_float4(a.z, c.z, a.w, c.w);
            }
        }
    }

    // ---- each pair stages its own bone copy (72 u64) ----
    const int b = bid >> 5;                    // 32 blocks per batch item
    {
        float2* bt = (float2*)sm + BONES_OFF + pr * 72;
        #pragma unroll
        for (int i = ptid; i < 72; i += 64)    // R13 fix: stride covers all 72
            bt[i] = make_float2(Xt[b * 72 + i], Yt[b * 72 + i]);
    }
    pair_sync(pr);                             // only THIS pair's data must be ready

    const int lane = tid & 31;
    const int wid  = tid >> 5;                 // 0..3
    const int isB  = wid & 1;                  // even warp = half A, odd = half B
    const int row  = pr * 32 + lane;           // row within tile (0..63)

    const u64* r  = (const u64*)sm + (size_t)row * ROW;
    const u64* bn = (const u64*)sm + BONES_OFF + (size_t)pr * 72;
    u64* g9s      = (u64*)sm + G9_OFF + (size_t)row * 7;

    const unsigned FULL = 0xffffffffu;
    float acc = 0.f;

    // ---- root (both warps of a pair; half weights) ----
    PXf P0;
    {
        u64 w = r[0], x = r[1], y = r[2], z = r[3];
        u64 n2 = ml2(w, w); n2 = fm2(x, x, n2); n2 = fm2(y, y, n2); n2 = fm2(z, z, n2);
        float na, nb; upk2(n2, na, nb);
        u64 inv = pk2(rsqrtf(na), rsqrtf(nb));
        w = ml2(w, inv); x = ml2(x, inv); y = ml2(y, inv); z = ml2(z, inv);

        float s = 0.f;
        d2(w, s); d2(x, s); d2(y, s); d2(z, s);
        acc = fmaf(S1h, s, acc);

        P0.qw = w; P0.qx = x; P0.qy = y; P0.qz = z;
        P0.tx = r[96]; P0.ty = r[97]; P0.tz = r[98];
        float t = 0.f;
        d2(P0.tx, t); d2(P0.ty, t); d2(P0.tz, t);
        acc = fmaf(S23h, t, acc);
    }

    // ---- phase 1 ----
    PXf G9;                                    // A: chain 0->3->6->9 result
    if (!isB) {
        jstep(r, bn, 3, P0, G9, acc);
        jstep(r, bn, 6, G9, G9, acc);
        jstep(r, bn, 9, G9, G9, acc);
        g9s[0] = G9.qw; g9s[1] = G9.qx; g9s[2] = G9.qy; g9s[3] = G9.qz;
        g9s[4] = G9.tx; g9s[5] = G9.ty; g9s[6] = G9.tz;
    } else {
        PXf C;                                 // B: chain 0->2->5->8->11
        jstep(r, bn,  2, P0, C, acc);
        jstep(r, bn,  5, C,  C, acc);
        jstep(r, bn,  8, C,  C, acc);
        jstep(r, bn, 11, C,  C, acc);
    }
    pair_sync(pr);                             // publish G9 within the pair

    // ---- phase 2: two independent chains per thread, interleaved ----
    if (!isB) {
        PXf C1, C2;
        jstep(r, bn,  1, P0, C1, acc);
        jstep(r, bn, 13, G9, C2, acc);
        jstep(r, bn,  4, C1, C1, acc);
        jstep(r, bn, 16, C2, C2, acc);
        jstep(r, bn,  7, C1, C1, acc);
        jstep(r, bn, 18, C2, C2, acc);
        jstep(r, bn, 10, C1, C1, acc);
        jstep(r, bn, 20, C2, C2, acc);
        jstep(r, bn, 22, C2, C2, acc);
    } else {
        PXf P9;
        P9.qw = g9s[0]; P9.qx = g9s[1]; P9.qy = g9s[2]; P9.qz = g9s[3];
        P9.tx = g9s[4]; P9.ty = g9s[5]; P9.tz = g9s[6];
        PXf C1, C2;
        jstep(r, bn, 12, P9, C1, acc);
        jstep(r, bn, 14, P9, C2, acc);
        jstep(r, bn, 15, C1, C1, acc);
        jstep(r, bn, 17, C2, C2, acc);
        jstep(r, bn, 19, C2, C2, acc);
        jstep(r, bn, 21, C2, C2, acc);
        jstep(r, bn, 23, C2, C2, acc);
    }

    // ---- block reduction (4 warps) ----
    #pragma unroll
    for (int o = 16; o > 0; o >>= 1) acc += __shfl_xor_sync(FULL, acc, o);

    __shared__ float wsum[4];
    __shared__ int   s_last;
    if (lane == 0) wsum[wid] = acc;
    __syncthreads();

    if (tid == 0) {
        g_partials[bid] = wsum[0] + wsum[1] + wsum[2] + wsum[3];
        __threadfence();
        unsigned ticket = atomicAdd(&g_count, 1u);
        s_last = (ticket == NBLK - 1) ? 1 : 0;
    }
    __syncthreads();

    // ---- last block: deterministic fixed-order final sum ----
    if (s_last) {
        double v = 0.0;
        #pragma unroll
        for (int k = 0; k < NBLK / TPB; ++k)     // 16 per thread
            v += (double)g_partials[tid + k * TPB];

        __shared__ double dsum[TPB];
        dsum[tid] = v;
        __syncthreads();
        #pragma unroll
        for (int o = TPB / 2; o > 0; o >>= 1) {
            if (tid < o) dsum[tid] += dsum[tid + o];
            __syncthreads();
        }
        if (tid == 0) {
            out[0] = (float)dsum[0];
            g_count = 0;                          // reset for next graph replay
        }
    }
}

extern "C" void kernel_launch(void* const* d_in, const int* in_sizes, int n_in,
                              void* d_out, int out_size)
{
    (void)in_sizes; (void)n_in; (void)out_size;
    const float* Ym = (const float*)d_in[0];
    const float* Xm = (const float*)d_in[1];
    const float* Yt = (const float*)d_in[2];
    const float* Xt = (const float*)d_in[3];

    cudaFuncSetAttribute(motion_loss_kernel,
                         cudaFuncAttributeMaxDynamicSharedMemorySize, SMEM_BYTES);
    motion_loss_kernel<<<NBLK, TPB, SMEM_BYTES>>>(Ym, Xm, Yt, Xt, (float*)d_out);
}